// round 16
// baseline (speedup 1.0000x reference)
#include <cuda_runtime.h>
#include <cstdint>

// ---------------------------------------------------------------------------
// Single fused kernel: depth-2 TMA prefetch, 256-row tiles, TPB=128.
//   prologue: t0 issues TMA loads for tiles i and i+grid (bufs 0,1);
//             lanes 0..9 of warp 0 compose the 8 conv layers into A in
//             registers (no barriers), write A to smem; 1 syncthreads.
//   loop (tile i, buf b): prefetch tile i+2*grid into buf (b+2)%4, gated by
//             wait_group.read 1 (that buffer's store is 2 iters old ->
//             slack); mbar wait (load issued 2 iters ago -> hidden);
//             in-place float2 compute (stride 9 x 64-bit: conflict-free);
//             async bulk store (no wait).
//   smem: 4*9216 + 448 + 32 = ~37 KB -> 6 CTAs/SM, 24 warps/SM,
//   16 loads in flight... (6 CTAs x 2) = 12 tile loads = 110 KB in flight.
// ---------------------------------------------------------------------------
#define TPB 128
#define RPT 2
#define ROWS_PER_TILE (TPB * RPT)            // 256
#define WORDS_PER_TILE (ROWS_PER_TILE * 9)   // 2304
#define BYTES_PER_TILE (WORDS_PER_TILE * 4)  // 9216
#define NBUF 4

__device__ __forceinline__ uint32_t smem_u32(const void* p) {
    uint32_t a;
    asm("{ .reg .u64 tmp; cvta.to.shared.u64 tmp, %1; cvt.u32.u64 %0, tmp; }"
        : "=r"(a) : "l"(p));
    return a;
}

__device__ __forceinline__ void mbar_wait(uint32_t mb, uint32_t parity) {
    uint32_t done;
    asm volatile(
        "{\n\t.reg .pred p;\n\t"
        "mbarrier.try_wait.parity.acquire.cta.shared::cta.b64 p, [%1], %2;\n\t"
        "selp.b32 %0, 1, 0, p;\n\t}"
        : "=r"(done) : "r"(mb), "r"(parity) : "memory");
    if (!done) {
        asm volatile(
            "{\n\t.reg .pred P1;\n\t"
            "WAIT_LOOP_%=:\n\t"
            "mbarrier.try_wait.parity.acquire.cta.shared::cta.b64 P1, [%0], %1, 0x989680;\n\t"
            "@P1 bra.uni WAIT_DONE_%=;\n\t"
            "bra.uni WAIT_LOOP_%=;\n\t"
            "WAIT_DONE_%=:\n\t}"
            :: "r"(mb), "r"(parity) : "memory");
    }
}

// issue one TMA tile load (called by t0 only)
__device__ __forceinline__ void tma_load_tile(uint32_t s_buf, uint32_t s_mb,
                                              const float* src) {
    asm volatile("mbarrier.arrive.expect_tx.shared.b64 _, [%0], %1;"
                 :: "r"(s_mb), "r"((uint32_t)BYTES_PER_TILE) : "memory");
    asm volatile(
        "cp.async.bulk.shared::cta.global.mbarrier::complete_tx::bytes "
        "[%0], [%1], %2, [%3];"
        :: "r"(s_buf), "l"(src), "r"((uint32_t)BYTES_PER_TILE), "r"(s_mb)
        : "memory");
}

__global__ __launch_bounds__(TPB, 6)
void affine_kernel(const float* __restrict__ x,
                   const float* __restrict__ w,    // [8*9]
                   const float* __restrict__ bias, // [8]
                   float* __restrict__ out,
                   int nrows) {
    __shared__ __align__(128) float sx[NBUF][WORDS_PER_TILE];
    __shared__ __align__(16) float sA[9 * 12];   // [w0..w8, bias, 0, 0] x 9
    __shared__ __align__(8) unsigned long long mbar[NBUF];

    int t = threadIdx.x;
    int ntiles = (nrows + ROWS_PER_TILE - 1) / ROWS_PER_TILE;
    int nfull  = nrows / ROWS_PER_TILE;          // tiles that are full

    if (t == 0) {
#pragma unroll
        for (int i = 0; i < NBUF; i++)
            asm volatile("mbarrier.init.shared.b64 [%0], %1;"
                         :: "r"(smem_u32(&mbar[i])), "r"(1) : "memory");
    }
    __syncthreads();

    uint32_t s_mb[NBUF], s_bf[NBUF];
#pragma unroll
    for (int i = 0; i < NBUF; i++) {
        s_mb[i] = smem_u32(&mbar[i]);
        s_bf[i] = smem_u32(sx[i]);
    }

    // ---- prologue: prefetch tiles 0 and 1 (depth 2) ----
    if (t == 0) {
        long long tile0 = blockIdx.x;
        if (tile0 < (long long)nfull)
            tma_load_tile(s_bf[0], s_mb[0], x + tile0 * (long long)WORDS_PER_TILE);
        long long tile1 = tile0 + gridDim.x;
        if (tile1 < (long long)nfull)
            tma_load_tile(s_bf[1], s_mb[1], x + tile1 * (long long)WORDS_PER_TILE);
    }

    // ---- compose A in registers, lanes 0..9 of warp 0; no barriers ----
    if (t < 10) {
        int c = t;               // column 0..8 = input elem, 9 = bias column
        float col[9];
#pragma unroll
        for (int o = 0; o < 9; o++) col[o] = (o == c) ? 1.0f : 0.0f;

        for (int d = 0; d < 8; d++) {
            float wd[9];
#pragma unroll
            for (int z = 0; z < 9; z++) wd[z] = __ldg(&w[d * 9 + z]);

            float nc[9];
#pragma unroll
            for (int o = 0; o < 9; o++) {
                int i = o / 3, j = o % 3;
                float acc = 0.0f;
#pragma unroll
                for (int di = -1; di <= 1; di++) {
#pragma unroll
                    for (int dj = -1; dj <= 1; dj++) {
                        int ii = i + di, jj = j + dj;
                        if (ii >= 0 && ii < 3 && jj >= 0 && jj < 3)
                            acc += wd[(di + 1) * 3 + (dj + 1)] * col[ii * 3 + jj];
                    }
                }
                nc[o] = acc;
            }
            float bd = (c == 9) ? __ldg(&bias[d]) : 0.0f;
#pragma unroll
            for (int o = 0; o < 9; o++) col[o] = nc[o] + bd;
        }

#pragma unroll
        for (int o = 0; o < 9; o++) sA[o * 12 + c] = col[o];
        if (c < 9) { sA[c * 12 + 10] = 0.0f; sA[c * 12 + 11] = 0.0f; }
    }
    __syncthreads();   // A visible to all warps

    uint32_t ph[NBUF] = {0u, 0u, 0u, 0u};
    int b = 0;
    for (long long tile = blockIdx.x; tile < ntiles; tile += gridDim.x) {
        int bn  = (b + 1) & (NBUF - 1);
        int bnn = (b + 2) & (NBUF - 1);
        float* buf = sx[b];

        long long r0 = tile * ROWS_PER_TILE;
        int rows_here = (int)((((long long)nrows - r0) < ROWS_PER_TILE)
                                  ? (nrows - r0) : ROWS_PER_TILE);
        bool full = (rows_here == ROWS_PER_TILE);
        int cnt = rows_here * 9;
        const float* xg = x + r0 * 9;
        float*       og = out + r0 * 9;

        // ---- prefetch tile+2*grid into buffer bnn ----
        long long ptile = tile + 2LL * gridDim.x;
        if (ptile < (long long)nfull && t == 0) {
            // buffer bnn's store was issued 2 iterations ago; allow the
            // most recent store to stay outstanding
            asm volatile("cp.async.bulk.wait_group.read 1;" ::: "memory");
            tma_load_tile(s_bf[bnn], s_mb[bnn],
                          x + ptile * (long long)WORDS_PER_TILE);
        }

        if (full) {
            // ---- consume TMA-loaded tile (load issued 2 iters ago) ----
            mbar_wait(s_mb[b], ph[b]);
            ph[b] ^= 1;

            float* chunk = &buf[t * 18];  // this thread's 2 rows (72 B)
            float v[18];
            float y[18];

            // float2 loads: stride 9 in 64-bit units -> conflict-free
#pragma unroll
            for (int k = 0; k < 9; k++)
                *(float2*)&v[2 * k] = *(const float2*)&chunk[2 * k];

            const float* xa = v;
            const float* xb = v + 9;

#pragma unroll
            for (int o = 0; o < 9; o++) {
                float4 a0 = *(const float4*)&sA[o * 12 + 0];
                float4 a1 = *(const float4*)&sA[o * 12 + 4];
                float4 a2 = *(const float4*)&sA[o * 12 + 8]; // x=w8, y=bias

                float acc = fmaf(a0.x, xa[0], a2.y);
                acc = fmaf(a0.y, xa[1], acc);
                acc = fmaf(a0.z, xa[2], acc);
                acc = fmaf(a0.w, xa[3], acc);
                acc = fmaf(a1.x, xa[4], acc);
                acc = fmaf(a1.y, xa[5], acc);
                acc = fmaf(a1.z, xa[6], acc);
                acc = fmaf(a1.w, xa[7], acc);
                y[o] = fmaf(a2.x, xa[8], acc);

                float acd = fmaf(a0.x, xb[0], a2.y);
                acd = fmaf(a0.y, xb[1], acd);
                acd = fmaf(a0.z, xb[2], acd);
                acd = fmaf(a0.w, xb[3], acd);
                acd = fmaf(a1.x, xb[4], acd);
                acd = fmaf(a1.y, xb[5], acd);
                acd = fmaf(a1.z, xb[6], acd);
                acd = fmaf(a1.w, xb[7], acd);
                y[9 + o] = fmaf(a2.x, xb[8], acd);
            }

#pragma unroll
            for (int k = 0; k < 9; k++)
                *(float2*)&chunk[2 * k] = *(const float2*)&y[2 * k];

            __syncthreads();  // all y written before async store reads smem
            if (t == 0) {
                asm volatile("fence.proxy.async.shared::cta;" ::: "memory");
                asm volatile(
                    "cp.async.bulk.global.shared::cta.bulk_group [%0], [%1], %2;"
                    :: "l"(og), "r"(s_bf[b]), "r"((uint32_t)BYTES_PER_TILE)
                    : "memory");
                asm volatile("cp.async.bulk.commit_group;" ::: "memory");
            }
            // no wait: store drains while we move on
        } else {
            // ---- partial tile: synchronous fallback path ----
            if (t == 0) {
                asm volatile("cp.async.bulk.wait_group.read 0;" ::: "memory");
            }
            __syncthreads();
#pragma unroll
            for (int k = 0; k < (WORDS_PER_TILE + TPB * 4 - 1) / (TPB * 4); k++) {
                int fi = (k * TPB + t) * 4;
                if (fi + 4 <= cnt) {
                    *(float4*)&buf[fi] = *(const float4*)&xg[fi];
                } else if (fi < cnt) {
                    for (int u = fi; u < cnt; u++) buf[u] = xg[u];
                }
            }
            __syncthreads();
            int lr0 = t * RPT;
            for (int lr = lr0; lr < lr0 + RPT && lr < rows_here; lr++) {
                float xp[9];
#pragma unroll
                for (int c = 0; c < 9; c++) xp[c] = buf[lr * 9 + c];
#pragma unroll
                for (int o = 0; o < 9; o++) {
                    float acc = sA[o * 12 + 9];
#pragma unroll
                    for (int c = 0; c < 9; c++)
                        acc = fmaf(sA[o * 12 + c], xp[c], acc);
                    buf[lr * 9 + o] = acc;
                }
            }
            __syncthreads();
#pragma unroll
            for (int k = 0; k < (WORDS_PER_TILE + TPB * 4 - 1) / (TPB * 4); k++) {
                int fi = (k * TPB + t) * 4;
                if (fi + 4 <= cnt) {
                    *(float4*)&og[fi] = *(const float4*)&buf[fi];
                } else if (fi < cnt) {
                    for (int u = fi; u < cnt; u++) og[u] = buf[u];
                }
            }
        }

        b = bn;
    }

    // drain the last async stores before exit
    if (t == 0) {
        asm volatile("cp.async.bulk.wait_group 0;" ::: "memory");
    }
}

extern "C" void kernel_launch(void* const* d_in, const int* in_sizes, int n_in,
                              void* d_out, int out_size) {
    const float* x = (const float*)d_in[0];  // [N*9]
    const float* w = (const float*)d_in[1];  // [8*9]
    const float* b = (const float*)d_in[2];  // [8]
    float* out = (float*)d_out;              // [N*9]

    int nrows = in_sizes[0] / 9;

    int ntiles = (nrows + ROWS_PER_TILE - 1) / ROWS_PER_TILE;
    int blocks = 148 * 6;
    if (blocks > ntiles) blocks = ntiles;
    affine_kernel<<<blocks, TPB>>>(x, w, b, out, nrows);
}

// round 17
// speedup vs baseline: 1.0498x; 1.0498x over previous
#include <cuda_runtime.h>
#include <cstdint>

// ---------------------------------------------------------------------------
// Single fused kernel: depth-2 TMA prefetch, 256-row tiles, TPB=64,
// registers capped at 128 via __launch_bounds__(64,8).
//   prologue: t0 issues TMA loads for tiles i and i+grid (bufs 0,1);
//             lanes 0..9 of warp 0 compose the 8 conv layers into A in
//             registers (no barriers), write A to smem; 1 syncthreads.
//   loop (tile i, buf b): prefetch tile i+2*grid into buf (b+2)%4, gated by
//             wait_group.read 1 (that buffer's store is 2 iters old ->
//             slack); mbar wait (load issued 2 iters ago -> hidden);
//             in-place float4 compute (2 row-groups, 144 B chunks);
//             async bulk store (no wait).
//   smem: 4*9216 + 448 + 32 = ~36.5 KB -> 6 CTAs/SM; 12 tile loads in
//   flight per SM (~110 KB).
// ---------------------------------------------------------------------------
#define TPB 64
#define RPT 4
#define ROWS_PER_TILE (TPB * RPT)            // 256
#define WORDS_PER_TILE (ROWS_PER_TILE * 9)   // 2304
#define BYTES_PER_TILE (WORDS_PER_TILE * 4)  // 9216
#define NBUF 4

__device__ __forceinline__ uint32_t smem_u32(const void* p) {
    uint32_t a;
    asm("{ .reg .u64 tmp; cvta.to.shared.u64 tmp, %1; cvt.u32.u64 %0, tmp; }"
        : "=r"(a) : "l"(p));
    return a;
}

__device__ __forceinline__ void mbar_wait(uint32_t mb, uint32_t parity) {
    uint32_t done;
    asm volatile(
        "{\n\t.reg .pred p;\n\t"
        "mbarrier.try_wait.parity.acquire.cta.shared::cta.b64 p, [%1], %2;\n\t"
        "selp.b32 %0, 1, 0, p;\n\t}"
        : "=r"(done) : "r"(mb), "r"(parity) : "memory");
    if (!done) {
        asm volatile(
            "{\n\t.reg .pred P1;\n\t"
            "WAIT_LOOP_%=:\n\t"
            "mbarrier.try_wait.parity.acquire.cta.shared::cta.b64 P1, [%0], %1, 0x989680;\n\t"
            "@P1 bra.uni WAIT_DONE_%=;\n\t"
            "bra.uni WAIT_LOOP_%=;\n\t"
            "WAIT_DONE_%=:\n\t}"
            :: "r"(mb), "r"(parity) : "memory");
    }
}

// issue one TMA tile load (called by t0 only)
__device__ __forceinline__ void tma_load_tile(uint32_t s_buf, uint32_t s_mb,
                                              const float* src) {
    asm volatile("mbarrier.arrive.expect_tx.shared.b64 _, [%0], %1;"
                 :: "r"(s_mb), "r"((uint32_t)BYTES_PER_TILE) : "memory");
    asm volatile(
        "cp.async.bulk.shared::cta.global.mbarrier::complete_tx::bytes "
        "[%0], [%1], %2, [%3];"
        :: "r"(s_buf), "l"(src), "r"((uint32_t)BYTES_PER_TILE), "r"(s_mb)
        : "memory");
}

__global__ __launch_bounds__(TPB, 8)
void affine_kernel(const float* __restrict__ x,
                   const float* __restrict__ w,    // [8*9]
                   const float* __restrict__ bias, // [8]
                   float* __restrict__ out,
                   int nrows) {
    __shared__ __align__(128) float sx[NBUF][WORDS_PER_TILE];
    __shared__ __align__(16) float sA[9 * 12];   // [w0..w8, bias, 0, 0] x 9
    __shared__ __align__(8) unsigned long long mbar[NBUF];

    int t = threadIdx.x;
    int ntiles = (nrows + ROWS_PER_TILE - 1) / ROWS_PER_TILE;
    int nfull  = nrows / ROWS_PER_TILE;          // tiles that are full

    if (t == 0) {
#pragma unroll
        for (int i = 0; i < NBUF; i++)
            asm volatile("mbarrier.init.shared.b64 [%0], %1;"
                         :: "r"(smem_u32(&mbar[i])), "r"(1) : "memory");
    }
    __syncthreads();

    uint32_t s_mb[NBUF], s_bf[NBUF];
#pragma unroll
    for (int i = 0; i < NBUF; i++) {
        s_mb[i] = smem_u32(&mbar[i]);
        s_bf[i] = smem_u32(sx[i]);
    }

    // ---- prologue: prefetch tiles 0 and 1 (depth 2) ----
    if (t == 0) {
        long long tile0 = blockIdx.x;
        if (tile0 < (long long)nfull)
            tma_load_tile(s_bf[0], s_mb[0], x + tile0 * (long long)WORDS_PER_TILE);
        long long tile1 = tile0 + gridDim.x;
        if (tile1 < (long long)nfull)
            tma_load_tile(s_bf[1], s_mb[1], x + tile1 * (long long)WORDS_PER_TILE);
    }

    // ---- compose A in registers, lanes 0..9 of warp 0; no barriers ----
    if (t < 10) {
        int c = t;               // column 0..8 = input elem, 9 = bias column
        float col[9];
#pragma unroll
        for (int o = 0; o < 9; o++) col[o] = (o == c) ? 1.0f : 0.0f;

        for (int d = 0; d < 8; d++) {
            float wd[9];
#pragma unroll
            for (int z = 0; z < 9; z++) wd[z] = __ldg(&w[d * 9 + z]);

            float nc[9];
#pragma unroll
            for (int o = 0; o < 9; o++) {
                int i = o / 3, j = o % 3;
                float acc = 0.0f;
#pragma unroll
                for (int di = -1; di <= 1; di++) {
#pragma unroll
                    for (int dj = -1; dj <= 1; dj++) {
                        int ii = i + di, jj = j + dj;
                        if (ii >= 0 && ii < 3 && jj >= 0 && jj < 3)
                            acc += wd[(di + 1) * 3 + (dj + 1)] * col[ii * 3 + jj];
                    }
                }
                nc[o] = acc;
            }
            float bd = (c == 9) ? __ldg(&bias[d]) : 0.0f;
#pragma unroll
            for (int o = 0; o < 9; o++) col[o] = nc[o] + bd;
        }

#pragma unroll
        for (int o = 0; o < 9; o++) sA[o * 12 + c] = col[o];
        if (c < 9) { sA[c * 12 + 10] = 0.0f; sA[c * 12 + 11] = 0.0f; }
    }
    __syncthreads();   // A visible to all warps

    uint32_t ph[NBUF] = {0u, 0u, 0u, 0u};
    int b = 0;
    for (long long tile = blockIdx.x; tile < ntiles; tile += gridDim.x) {
        int bn  = (b + 1) & (NBUF - 1);
        int bnn = (b + 2) & (NBUF - 1);
        float* buf = sx[b];

        long long r0 = tile * ROWS_PER_TILE;
        int rows_here = (int)((((long long)nrows - r0) < ROWS_PER_TILE)
                                  ? (nrows - r0) : ROWS_PER_TILE);
        bool full = (rows_here == ROWS_PER_TILE);
        int cnt = rows_here * 9;
        const float* xg = x + r0 * 9;
        float*       og = out + r0 * 9;

        // ---- prefetch tile+2*grid into buffer bnn ----
        long long ptile = tile + 2LL * gridDim.x;
        if (ptile < (long long)nfull && t == 0) {
            // buffer bnn's store was issued 2 iterations ago; allow the
            // most recent store to stay outstanding
            asm volatile("cp.async.bulk.wait_group.read 1;" ::: "memory");
            tma_load_tile(s_bf[bnn], s_mb[bnn],
                          x + ptile * (long long)WORDS_PER_TILE);
        }

        if (full) {
            // ---- consume TMA-loaded tile (load issued 2 iters ago) ----
            mbar_wait(s_mb[b], ph[b]);
            ph[b] ^= 1;

            float* chunk = &buf[t * 36];   // this thread's 4 rows (144 B)
            float v[20];
            float y[18];

#pragma unroll
            for (int g = 0; g < 2; g++) {
                // group 0: rows 0,1 (words 0..17),  window = words 0..19
                // group 1: rows 2,3 (words 18..35), window = words 16..35
#pragma unroll
                for (int k = 0; k < 5; k++)
                    *(float4*)&v[4 * k] = *(const float4*)&chunk[16 * g + 4 * k];

                const float* xa = v + (g ? 2 : 0);
                const float* xb = xa + 9;

#pragma unroll
                for (int o = 0; o < 9; o++) {
                    float4 a0 = *(const float4*)&sA[o * 12 + 0];
                    float4 a1 = *(const float4*)&sA[o * 12 + 4];
                    float4 a2 = *(const float4*)&sA[o * 12 + 8]; // x=w8, y=bias

                    float acc = fmaf(a0.x, xa[0], a2.y);
                    acc = fmaf(a0.y, xa[1], acc);
                    acc = fmaf(a0.z, xa[2], acc);
                    acc = fmaf(a0.w, xa[3], acc);
                    acc = fmaf(a1.x, xa[4], acc);
                    acc = fmaf(a1.y, xa[5], acc);
                    acc = fmaf(a1.z, xa[6], acc);
                    acc = fmaf(a1.w, xa[7], acc);
                    y[o] = fmaf(a2.x, xa[8], acc);

                    float acd = fmaf(a0.x, xb[0], a2.y);
                    acd = fmaf(a0.y, xb[1], acd);
                    acd = fmaf(a0.z, xb[2], acd);
                    acd = fmaf(a0.w, xb[3], acd);
                    acd = fmaf(a1.x, xb[4], acd);
                    acd = fmaf(a1.y, xb[5], acd);
                    acd = fmaf(a1.z, xb[6], acd);
                    acd = fmaf(a1.w, xb[7], acd);
                    y[9 + o] = fmaf(a2.x, xb[8], acd);
                }

                if (g == 0) {
                    *(float4*)&chunk[0]  = *(const float4*)&y[0];
                    *(float4*)&chunk[4]  = *(const float4*)&y[4];
                    *(float4*)&chunk[8]  = *(const float4*)&y[8];
                    *(float4*)&chunk[12] = *(const float4*)&y[12];
                    *(float2*)&chunk[16] = *(const float2*)&y[16];
                } else {
                    *(float2*)&chunk[18] = *(const float2*)&y[0];
                    *(float4*)&chunk[20] = *(const float4*)&y[2];
                    *(float4*)&chunk[24] = *(const float4*)&y[6];
                    *(float4*)&chunk[28] = *(const float4*)&y[10];
                    *(float4*)&chunk[32] = *(const float4*)&y[14];
                }
            }

            __syncthreads();  // all y written before async store reads smem
            if (t == 0) {
                asm volatile("fence.proxy.async.shared::cta;" ::: "memory");
                asm volatile(
                    "cp.async.bulk.global.shared::cta.bulk_group [%0], [%1], %2;"
                    :: "l"(og), "r"(s_bf[b]), "r"((uint32_t)BYTES_PER_TILE)
                    : "memory");
                asm volatile("cp.async.bulk.commit_group;" ::: "memory");
            }
            // no wait: store drains while we move on
        } else {
            // ---- partial tile: synchronous fallback path ----
            if (t == 0) {
                asm volatile("cp.async.bulk.wait_group.read 0;" ::: "memory");
            }
            __syncthreads();
#pragma unroll
            for (int k = 0; k < (WORDS_PER_TILE + TPB * 4 - 1) / (TPB * 4); k++) {
                int fi = (k * TPB + t) * 4;
                if (fi + 4 <= cnt) {
                    *(float4*)&buf[fi] = *(const float4*)&xg[fi];
                } else if (fi < cnt) {
                    for (int u = fi; u < cnt; u++) buf[u] = xg[u];
                }
            }
            __syncthreads();
            int lr0 = t * RPT;
            for (int lr = lr0; lr < lr0 + RPT && lr < rows_here; lr++) {
                float xp[9];
#pragma unroll
                for (int c = 0; c < 9; c++) xp[c] = buf[lr * 9 + c];
#pragma unroll
                for (int o = 0; o < 9; o++) {
                    float acc = sA[o * 12 + 9];
#pragma unroll
                    for (int c = 0; c < 9; c++)
                        acc = fmaf(sA[o * 12 + c], xp[c], acc);
                    buf[lr * 9 + o] = acc;
                }
            }
            __syncthreads();
#pragma unroll
            for (int k = 0; k < (WORDS_PER_TILE + TPB * 4 - 1) / (TPB * 4); k++) {
                int fi = (k * TPB + t) * 4;
                if (fi + 4 <= cnt) {
                    *(float4*)&og[fi] = *(const float4*)&buf[fi];
                } else if (fi < cnt) {
                    for (int u = fi; u < cnt; u++) og[u] = buf[u];
                }
            }
        }

        b = bn;
    }

    // drain the last async stores before exit
    if (t == 0) {
        asm volatile("cp.async.bulk.wait_group 0;" ::: "memory");
    }
}

extern "C" void kernel_launch(void* const* d_in, const int* in_sizes, int n_in,
                              void* d_out, int out_size) {
    const float* x = (const float*)d_in[0];  // [N*9]
    const float* w = (const float*)d_in[1];  // [8*9]
    const float* b = (const float*)d_in[2];  // [8]
    float* out = (float*)d_out;              // [N*9]

    int nrows = in_sizes[0] / 9;

    int ntiles = (nrows + ROWS_PER_TILE - 1) / ROWS_PER_TILE;
    int blocks = 148 * 6;
    if (blocks > ntiles) blocks = ntiles;
    affine_kernel<<<blocks, TPB>>>(x, w, b, out, nrows);
}